// round 11
// baseline (speedup 1.0000x reference)
#include <cuda_runtime.h>
#include <math.h>

// ---------------- problem constants ----------------
#define B_    4
#define S_    2048
#define DIM_  1024
#define NH_   8
#define DH_   128
#define CS_   16
#define NS_   128
#define BH_   (B_*NH_)        // 32
#define NCHUNK (BH_*NS_)      // 4096
#define ET_   32              // e-tile width in fused kernel
#define EPS_    1e-6f
#define LN_EPS_ 1e-5f
#define NEG_   -1e30f
#define SCALE_    0.08838834764831845f   // 1/sqrt(128)
#define INVSCALE_ 11.313708498984761f    // sqrt(128)

typedef unsigned long long ull;

// ---------------- f32x2 packed helpers (sm_103a) ----------------
__device__ __forceinline__ ull pk2(float lo, float hi) {
    ull r; asm("mov.b64 %0, {%1, %2};" : "=l"(r) : "f"(lo), "f"(hi)); return r;
}
__device__ __forceinline__ ull ffma2(ull a, ull b, ull c) {
    ull d; asm("fma.rn.f32x2 %0, %1, %2, %3;" : "=l"(d) : "l"(a), "l"(b), "l"(c)); return d;
}
__device__ __forceinline__ ull fmul2(ull a, ull b) {
    ull d; asm("mul.rn.f32x2 %0, %1, %2;" : "=l"(d) : "l"(a), "l"(b)); return d;
}
__device__ __forceinline__ void upk2(ull v, float& lo, float& hi) {
    asm("mov.b64 {%0, %1}, %2;" : "=f"(lo), "=f"(hi) : "l"(v));
}

// ---------------- scratch (device globals; no allocation) ----------------
__device__ float g_ig   [BH_*S_];
__device__ float g_fg   [BH_*S_];
__device__ float g_lfacc[BH_*S_];
__device__ float g_gexp [BH_*S_];
__device__ float g_mp   [NCHUNK];
__device__ float g_a    [NCHUNK];
__device__ float g_b    [NCHUNK];
__device__ float g_E    [NCHUNK*CS_*CS_]; // unnormalized E per chunk (16x16)
__device__ float g_X    [NCHUNK*CS_*CS_]; // cross q_n.k_{n-1} (scaled), odd chunks
__device__ float g_qs   [NCHUNK*CS_];     // decay*scale per (chunk,c)
__device__ float g_esum [NCHUNK*CS_];     // row sums of E
__device__ float g_expns[NCHUNK*CS_];     // exp(-stab) per (chunk,c)

// ============================================================
// K1: gates (proven K1_T=8 config).
// ============================================================
#define K1_T 8
__global__ __launch_bounds__(256) void k_gates(
    const float* __restrict__ q, const float* __restrict__ k,
    const float* __restrict__ v, const float* __restrict__ Wi,
    const float* __restrict__ bi, const float* __restrict__ Wf,
    const float* __restrict__ bf)
{
    __shared__ float sg[K1_T][1024];
    int tid  = threadIdx.x;
    int base = blockIdx.x * K1_T;
    int w    = tid >> 5;
    int lane = tid & 31;
    const float* wi = Wi + w*3072;
    const float* wf = Wf + w*3072;

    float acc_i[K1_T], acc_f[K1_T];
#pragma unroll
    for (int t = 0; t < K1_T; t++) { acc_i[t] = 0.f; acc_f[t] = 0.f; }

    for (int seg = 0; seg < 3; seg++) {
        const float* src = (seg == 0) ? q : (seg == 1) ? k : v;
        for (int r = tid; r < K1_T*256; r += 256) {
            int t = r >> 8, d4 = r & 255;
            ((float4*)sg[t])[d4] =
                ((const float4*)(src + (size_t)(base + t)*1024))[d4];
        }
        __syncthreads();
        const float* wis = wi + seg*1024;
        const float* wfs = wf + seg*1024;
#pragma unroll 2
        for (int kk = lane*4; kk < 1024; kk += 128) {
            float4 w4i = *(const float4*)&wis[kk];
            float4 w4f = *(const float4*)&wfs[kk];
#pragma unroll
            for (int t = 0; t < K1_T; t++) {
                float4 g4 = *(const float4*)&sg[t][kk];
                acc_i[t] = fmaf(g4.x, w4i.x, acc_i[t]);
                acc_i[t] = fmaf(g4.y, w4i.y, acc_i[t]);
                acc_i[t] = fmaf(g4.z, w4i.z, acc_i[t]);
                acc_i[t] = fmaf(g4.w, w4i.w, acc_i[t]);
                acc_f[t] = fmaf(g4.x, w4f.x, acc_f[t]);
                acc_f[t] = fmaf(g4.y, w4f.y, acc_f[t]);
                acc_f[t] = fmaf(g4.z, w4f.z, acc_f[t]);
                acc_f[t] = fmaf(g4.w, w4f.w, acc_f[t]);
            }
        }
        __syncthreads();
    }
#pragma unroll
    for (int t = 0; t < K1_T; t++) {
#pragma unroll
        for (int off = 16; off; off >>= 1) {
            acc_i[t] += __shfl_xor_sync(0xffffffffu, acc_i[t], off);
            acc_f[t] += __shfl_xor_sync(0xffffffffu, acc_f[t], off);
        }
    }
    if (lane == 0) {
        float biv = bi[w], bfv = bf[w];
#pragma unroll
        for (int t = 0; t < K1_T; t++) {
            int bs = base + t;
            int b = bs >> 11, s = bs & 2047;
            int idx = (b*NH_ + w)*S_ + s;
            g_ig[idx] = acc_i[t] + biv;
            g_fg[idx] = acc_f[t] + bfv;
        }
    }
}

// ============================================================
// K2: per-bh prep: logsigmoid cumsum, gexp, (a,b,mp) max-plus scan.
// ============================================================
__global__ __launch_bounds__(128) void k_prep(float* __restrict__ ml_out)
{
    __shared__ float wLs[4], wMs[4];
    int bh = blockIdx.x;
    int n  = threadIdx.x;
    int lane = n & 31, wid = n >> 5;
    int base = bh*S_ + n*16;

    float fg[16], ig[16];
#pragma unroll
    for (int i = 0; i < 4; i++) {
        float4 f4 = *(const float4*)&g_fg[base + i*4];
        float4 i4 = *(const float4*)&g_ig[base + i*4];
        fg[i*4+0]=f4.x; fg[i*4+1]=f4.y; fg[i*4+2]=f4.z; fg[i*4+3]=f4.w;
        ig[i*4+0]=i4.x; ig[i*4+1]=i4.y; ig[i*4+2]=i4.z; ig[i*4+3]=i4.w;
    }
    float lfacc[16];
    float acc = 0.f;
#pragma unroll
    for (int c = 0; c < 16; c++) {
        float f = fg[c];
        float lf = fminf(f, 0.f) - log1pf(expf(-fabsf(f)));
        acc += lf;
        lfacc[c] = acc;
    }
    float lfl = lfacc[15];
    float lg[16];
    float mloc = NEG_;
#pragma unroll
    for (int c = 0; c < 16; c++) {
        lg[c] = ig[c] - lfacc[c] + lfl;
        mloc = fmaxf(mloc, lg[c]);
    }
#pragma unroll
    for (int i = 0; i < 4; i++) {
        float4 a4, g4;
        a4.x=lfacc[i*4+0]; a4.y=lfacc[i*4+1]; a4.z=lfacc[i*4+2]; a4.w=lfacc[i*4+3];
        g4.x=expf(lg[i*4+0]-mloc); g4.y=expf(lg[i*4+1]-mloc);
        g4.z=expf(lg[i*4+2]-mloc); g4.w=expf(lg[i*4+3]-mloc);
        *(float4*)&g_lfacc[base + i*4] = a4;
        *(float4*)&g_gexp [base + i*4] = g4;
    }

    float L = lfl, M = mloc;
#pragma unroll
    for (int off = 1; off < 32; off <<= 1) {
        float Lp = __shfl_up_sync(0xffffffffu, L, off);
        float Mp = __shfl_up_sync(0xffffffffu, M, off);
        if (lane >= off) { M = fmaxf(Mp + L, M); L = Lp + L; }
    }
    if (lane == 31) { wLs[wid] = L; wMs[wid] = M; }
    __syncthreads();
    float PL = 0.f, PM = NEG_;
#pragma unroll
    for (int ww = 0; ww < 4; ww++) {
        if (ww < wid) { PM = fmaxf(PM + wLs[ww], wMs[ww]); PL += wLs[ww]; }
    }
    float Lex_w = __shfl_up_sync(0xffffffffu, L, 1);
    float Mex_w = __shfl_up_sync(0xffffffffu, M, 1);
    if (lane == 0) { Lex_w = 0.f; Mex_w = NEG_; }
    float Lex = PL + Lex_w;
    float Mex = fmaxf(PM + Lex_w, Mex_w);
    float mp = fmaxf(Lex, Mex);
    float Linc = PL + L;
    float Minc = fmaxf(PM + L, M);
    float m = fmaxf(Linc, Minc);

    int idx = bh*NS_ + n;
    g_a [idx] = expf(lfl + mp - m);
    g_b [idx] = expf(mloc - m);
    g_mp[idx] = mp;
    if (n == NS_-1) ml_out[bh] = m;
}

// ============================================================
// K3: Phase A per chunk: unnormalized E, Esum, decay, exp(-stab).
// Odd chunks additionally compute X = (q*scale) @ k_prev^T.
// ============================================================
#define PAD 129
__global__ __launch_bounds__(128) void k_phaseA(
    const float* __restrict__ qin, const float* __restrict__ kin)
{
    __shared__ float sq [CS_][PAD];
    __shared__ float sk [CS_][PAD];
    __shared__ float skp[CS_][PAD];
    __shared__ float slf[CS_], sig[CS_];
    __shared__ float smp;

    int chunk = blockIdx.x;
    int bh = chunk >> 7, n = chunk & 127;
    int b = bh >> 3, h = bh & 7;
    int tid = threadIdx.x;
    bool odd = (n & 1) != 0;

    for (int r = tid; r < CS_*DH_; r += 128) {
        int c = r >> 7, d = r & 127;
        size_t gidx = (size_t)(b*S_ + n*16 + c)*DIM_ + h*DH_ + d;
        sq[c][d] = qin[gidx] * SCALE_;
        sk[c][d] = kin[gidx];
        if (odd) skp[c][d] = kin[gidx - (size_t)16*DIM_];
    }
    if (tid < 16) {
        slf[tid] = g_lfacc[bh*S_ + n*16 + tid];
        sig[tid] = g_ig  [bh*S_ + n*16 + tid];
    }
    if (tid == 0) smp = g_mp[chunk];
    __syncthreads();

    int c  = tid >> 3;
    int jj = tid & 7;
    int j0 = 2*jj, j1 = 2*jj + 1;
    float qk0 = 0.f, qk1 = 0.f;
#pragma unroll 4
    for (int d = 0; d < DH_; d++) {
        float qv = sq[c][d];
        qk0 = fmaf(qv, sk[j0][d], qk0);
        qk1 = fmaf(qv, sk[j1][d], qk1);
    }
    float mp  = smp;
    float lD0 = ((j0 > c) ? NEG_ : (slf[c] - slf[j0])) + sig[j0];
    float lD1 = ((j1 > c) ? NEG_ : (slf[c] - slf[j1])) + sig[j1];
    float mrow = fmaxf(lD0, lD1);
#pragma unroll
    for (int off = 4; off; off >>= 1)
        mrow = fmaxf(mrow, __shfl_xor_sync(0xffffffffu, mrow, off, 8));
    float stab  = fmaxf(mrow, mp + slf[c]);
    float decay = expf(mp + slf[c] - stab);
    float E0 = qk0 * expf(lD0 - stab);
    float E1 = qk1 * expf(lD1 - stab);
    float Esum = E0 + E1;
#pragma unroll
    for (int off = 4; off; off >>= 1)
        Esum += __shfl_xor_sync(0xffffffffu, Esum, off, 8);
    g_E[chunk*256 + c*16 + j0] = E0;
    g_E[chunk*256 + c*16 + j1] = E1;
    if (jj == 0) {
        g_qs   [chunk*16 + c] = decay * SCALE_;
        g_esum [chunk*16 + c] = Esum;
        g_expns[chunk*16 + c] = expf(-stab);
    }
    if (odd) {
        float x0 = 0.f, x1 = 0.f;
#pragma unroll 4
        for (int d = 0; d < DH_; d++) {
            float qv = sq[c][d];
            x0 = fmaf(qv, skp[j0][d], x0);
            x1 = fmaf(qv, skp[j1][d], x1);
        }
        g_X[chunk*256 + c*16 + j0] = x0;
        g_X[chunk*256 + c*16 + j1] = x1;
    }
}

// ============================================================
// K4: fused scan + output (v9): CHUNK-PAIRED.
// Per pair (n0=2t, n1=2t+1): C read once, rank-32 update once,
// 2 barriers per PAIR. Odd-chunk inter via cross-term:
//   h1raw = qs1*a0*(q1@C) + qs1*b0*(M@v0) + E1@v1,
//   M = X_raw .* g0;  pn1 = a0*(q1.sn) + b0*rowsum(M).
//  warps 0-7 : inter (K-split 16), both chunks; spart0/1
//  warps 8-15: C update rank-32 + ksum; republish + sn in phase 2
//  phase 2   : tid<128 epilogue for both chunks
// ============================================================
struct __align__(16) SM9 {
    float sq[2][CS_][132];
    float sk[2][CS_][132];
    float sv[2][CS_][36];
    float sE[2][CS_][17];
    float sX[CS_][17];
    float spart[2][8][CS_][36];
    float spn[2][8][CS_];
    float sC[DH_][ET_];
    float sn[DH_];
    float sg0[CS_], sg1[CS_], sqs0[CS_], sqs1[CS_];
    float sab[4];
};

__global__ __launch_bounds__(512, 1) void k_fused9(
    const float* __restrict__ qin, const float* __restrict__ kin,
    const float* __restrict__ vin, float* __restrict__ out,
    float* __restrict__ Cl, float* __restrict__ nl)
{
    extern __shared__ char smraw[];
    SM9* sm = (SM9*)smraw;

    int et = blockIdx.x;      // 0..3
    int bh = blockIdx.y;      // 0..31
    int b = bh >> 3, h = bh & 7;
    int tid = threadIdx.x;
    int wid = tid >> 5;
    int lane = tid & 31;

    size_t rowbase = (size_t)(b*S_)*DIM_ + h*DH_;

    // zero state
    for (int i = tid; i < DH_*ET_; i += 512) (&sm->sC[0][0])[i] = 0.f;
    if (tid < DH_) sm->sn[tid] = 0.f;

    // staging map: thread (c16, l32)
    int c16 = tid >> 5, l32 = tid & 31;
    // inter map
    int cgi = lane >> 3, eg = lane & 7;
    // update map
    int utid = tid - 256;
    int ux = utid & 15, uyy = (utid >= 0) ? (utid >> 4) : 0;

    float Cf[8][2];
#pragma unroll
    for (int g = 0; g < 8; g++) { Cf[g][0] = 0.f; Cf[g][1] = 0.f; }

    // prefetch regs
    float4 qrA, qrB, krA, krB;
    float4 vr = make_float4(0.f,0.f,0.f,0.f);
    float cE = 0.f, cX = 0.f, cg_ = 0.f, cqs = 0.f, cab = 0.f;
    float nqs0=0.f, nes0=0.f, nxs0=0.f, nqs1=0.f, nes1=0.f, nxs1=0.f;

    {   // prefetch pair 0
        int n0 = 0, n1 = 1;
        int chunk0 = bh*NS_, chunk1 = chunk0 + 1;
        const float* qr0p = qin + rowbase + (size_t)(n0*16 + c16)*DIM_;
        const float* qr1p = qin + rowbase + (size_t)(n1*16 + c16)*DIM_;
        const float* kr0p = kin + rowbase + (size_t)(n0*16 + c16)*DIM_;
        const float* kr1p = kin + rowbase + (size_t)(n1*16 + c16)*DIM_;
        qrA = ((const float4*)qr0p)[l32];
        qrB = ((const float4*)qr1p)[l32];
        krA = ((const float4*)kr0p)[l32];
        krB = ((const float4*)kr1p)[l32];
        if (tid < 256) {
            int t2 = tid & 127;
            int nn = (tid < 128) ? n0 : n1;
            vr = ((const float4*)(vin + rowbase + (size_t)(nn*16 + (t2>>3))*DIM_ + et*ET_))[t2 & 7];
            cE = g_E[chunk0*256 + tid];
        } else {
            int t2 = tid - 256;
            cE = g_E[chunk1*256 + t2];
            cX = g_X[chunk1*256 + t2];
        }
        if (tid < 16) { cg_ = g_gexp[bh*S_ + n0*16 + tid]; cqs = g_qs[chunk0*16 + tid]; }
        else if (tid < 32) { cg_ = g_gexp[bh*S_ + n1*16 + (tid-16)]; cqs = g_qs[chunk1*16 + (tid-16)]; }
        if (tid == 32) cab = g_a[chunk0];
        if (tid == 33) cab = g_b[chunk0];
        if (tid == 34) cab = g_a[chunk1];
        if (tid == 35) cab = g_b[chunk1];
        if (tid < 128) {
            int c = tid >> 3;
            nqs0 = g_qs[chunk0*16 + c]; nes0 = g_esum[chunk0*16 + c]; nxs0 = g_expns[chunk0*16 + c];
            nqs1 = g_qs[chunk1*16 + c]; nes1 = g_esum[chunk1*16 + c]; nxs1 = g_expns[chunk1*16 + c];
        }
    }

    for (int tt = 0; tt < NS_/2; tt++) {
        int n0 = tt*2;
        // ---- stage pair tt ----
        *(float4*)&sm->sq[0][c16][l32*4] = qrA;
        *(float4*)&sm->sq[1][c16][l32*4] = qrB;
        *(float4*)&sm->sk[0][c16][l32*4] = krA;
        *(float4*)&sm->sk[1][c16][l32*4] = krB;
        if (tid < 128) {
            *(float4*)&sm->sv[0][tid>>3][(tid&7)*4] = vr;
        } else if (tid < 256) {
            int t2 = tid - 128;
            *(float4*)&sm->sv[1][t2>>3][(t2&7)*4] = vr;
        }
        if (tid < 256) {
            sm->sE[0][tid>>4][tid&15] = cE;
        } else {
            int t2 = tid - 256;
            sm->sE[1][t2>>4][t2&15] = cE;
            sm->sX[t2>>4][t2&15]    = cX;
        }
        if (tid < 16) { sm->sg0[tid] = cg_; sm->sqs0[tid] = cqs; }
        else if (tid < 32) { sm->sg1[tid-16] = cg_; sm->sqs1[tid-16] = cqs; }
        if (tid >= 32 && tid < 36) sm->sab[tid-32] = cab;
        // carry epilogue consts to locals
        float rqs0 = nqs0, res0 = nes0, rxs0 = nxs0;
        float rqs1 = nqs1, res1 = nes1, rxs1 = nxs1;
        __syncthreads();

        // ---- prefetch pair tt+1 ----
        if (tt + 1 < NS_/2) {
            int m0 = n0 + 2, m1 = n0 + 3;
            int chunk0 = bh*NS_ + m0, chunk1 = chunk0 + 1;
            qrA = ((const float4*)(qin + rowbase + (size_t)(m0*16 + c16)*DIM_))[l32];
            qrB = ((const float4*)(qin + rowbase + (size_t)(m1*16 + c16)*DIM_))[l32];
            krA = ((const float4*)(kin + rowbase + (size_t)(m0*16 + c16)*DIM_))[l32];
            krB = ((const float4*)(kin + rowbase + (size_t)(m1*16 + c16)*DIM_))[l32];
            if (tid < 256) {
                int t2 = tid & 127;
                int nn = (tid < 128) ? m0 : m1;
                vr = ((const float4*)(vin + rowbase + (size_t)(nn*16 + (t2>>3))*DIM_ + et*ET_))[t2 & 7];
                cE = g_E[chunk0*256 + tid];
            } else {
                int t2 = tid - 256;
                cE = g_E[chunk1*256 + t2];
                cX = g_X[chunk1*256 + t2];
            }
            if (tid < 16) { cg_ = g_gexp[bh*S_ + m0*16 + tid]; cqs = g_qs[chunk0*16 + tid]; }
            else if (tid < 32) { cg_ = g_gexp[bh*S_ + m1*16 + (tid-16)]; cqs = g_qs[chunk1*16 + (tid-16)]; }
            if (tid == 32) cab = g_a[chunk0];
            if (tid == 33) cab = g_b[chunk0];
            if (tid == 34) cab = g_a[chunk1];
            if (tid == 35) cab = g_b[chunk1];
            if (tid < 128) {
                int c = tid >> 3;
                nqs0 = g_qs[chunk0*16 + c]; nes0 = g_esum[chunk0*16 + c]; nxs0 = g_expns[chunk0*16 + c];
                nqs1 = g_qs[chunk1*16 + c]; nes1 = g_esum[chunk1*16 + c]; nxs1 = g_expns[chunk1*16 + c];
            }
        }

        float ks = 0.f;       // update warps: fused ksum (scales folded)
        float Acar = 0.f;     // update warps: A = a0*a1 carried to phase 2
        if (tid < 256) {
            // ---- inter: K-split over both chunks ----
            ull accA[4][2], accB[4][2];
            float pnA[4], pnB[4];
#pragma unroll
            for (int i = 0; i < 4; i++) {
                accA[i][0]=0ull; accA[i][1]=0ull; accB[i][0]=0ull; accB[i][1]=0ull;
                pnA[i]=0.f; pnB[i]=0.f;
            }
            int k0 = wid * 16;
#pragma unroll
            for (int kk4 = 0; kk4 < 4; kk4++) {
                int kb = k0 + kk4*4;
                float4 sn4 = *(const float4*)&sm->sn[kb];
#pragma unroll
                for (int j = 0; j < 4; j++) {
                    ulonglong2 c2 = *(const ulonglong2*)&sm->sC[kb + j][eg*4];
                    float snv = ((const float*)&sn4)[j];
#pragma unroll
                    for (int i = 0; i < 4; i++) {
                        float qva = sm->sq[0][cgi + 4*i][kb + j];
                        ull qa2 = pk2(qva, qva);
                        accA[i][0] = ffma2(qa2, c2.x, accA[i][0]);
                        accA[i][1] = ffma2(qa2, c2.y, accA[i][1]);
                        pnA[i] = fmaf(qva, snv, pnA[i]);
                        float qvb = sm->sq[1][cgi + 4*i][kb + j];
                        ull qb2 = pk2(qvb, qvb);
                        accB[i][0] = ffma2(qb2, c2.x, accB[i][0]);
                        accB[i][1] = ffma2(qb2, c2.y, accB[i][1]);
                        pnB[i] = fmaf(qvb, snv, pnB[i]);
                    }
                }
            }
            float a0 = sm->sab[0], b0 = sm->sab[1];
            float qs1v[4];
#pragma unroll
            for (int i = 0; i < 4; i++) {
                int c = cgi + 4*i;
                float qsA = sm->sqs0[c];
                ull qA2 = pk2(qsA, qsA);
                accA[i][0] = fmul2(accA[i][0], qA2);
                accA[i][1] = fmul2(accA[i][1], qA2);
                float q1c = sm->sqs1[c];
                qs1v[i] = q1c;
                float cb = q1c * a0;
                ull cb2 = pk2(cb, cb);
                accB[i][0] = fmul2(accB[i][0], cb2);
                accB[i][1] = fmul2(accB[i][1], cb2);
                pnB[i] *= a0;
            }
            // E / M terms: rows r = wid*2 + rr
#pragma unroll
            for (int rr = 0; rr < 2; rr++) {
                int r = wid*2 + rr;
                ulonglong2 v0 = *(const ulonglong2*)&sm->sv[0][r][eg*4];
                ulonglong2 v1 = *(const ulonglong2*)&sm->sv[1][r][eg*4];
                float w0r = sm->sg0[r] * b0 * INVSCALE_;
#pragma unroll
                for (int i = 0; i < 4; i++) {
                    int c = cgi + 4*i;
                    float e0 = sm->sE[0][c][r];
                    ull e02 = pk2(e0, e0);
                    accA[i][0] = ffma2(e02, v0.x, accA[i][0]);
                    accA[i][1] = ffma2(e02, v0.y, accA[i][1]);
                    float e1 = sm->sE[1][c][r];
                    ull e12 = pk2(e1, e1);
                    accB[i][0] = ffma2(e12, v1.x, accB[i][0]);
                    accB[i][1] = ffma2(e12, v1.y, accB[i][1]);
                    float xv = sm->sX[c][r] * w0r;
                    pnB[i] += xv;
                    float mv = xv * qs1v[i];
                    ull m2 = pk2(mv, mv);
                    accB[i][0] = ffma2(m2, v0.x, accB[i][0]);
                    accB[i][1] = ffma2(m2, v0.y, accB[i][1]);
                }
            }
#pragma unroll
            for (int i = 0; i < 4; i++) {
                ulonglong2 stA; stA.x = accA[i][0]; stA.y = accA[i][1];
                *(ulonglong2*)&sm->spart[0][wid][cgi + 4*i][eg*4] = stA;
                ulonglong2 stB; stB.x = accB[i][0]; stB.y = accB[i][1];
                *(ulonglong2*)&sm->spart[1][wid][cgi + 4*i][eg*4] = stB;
            }
            if (eg == 0) {
#pragma unroll
                for (int i = 0; i < 4; i++) {
                    sm->spn[0][wid][cgi + 4*i] = pnA[i];
                    sm->spn[1][wid][cgi + 4*i] = pnB[i];
                }
            }
        } else {
            // ---- update: rank-32, scales folded ----
            float a0 = sm->sab[0], b0 = sm->sab[1];
            float a1 = sm->sab[2], b1 = sm->sab[3];
            float A  = a0 * a1;
            float s0 = a1 * b0;
            Acar = A;
            float sgr0[16], sgr1[16];
#pragma unroll
            for (int i = 0; i < 4; i++) {
                float4 g4 = *(const float4*)&sm->sg0[i*4];
                sgr0[i*4+0]=g4.x*s0; sgr0[i*4+1]=g4.y*s0; sgr0[i*4+2]=g4.z*s0; sgr0[i*4+3]=g4.w*s0;
                float4 g5 = *(const float4*)&sm->sg1[i*4];
                sgr1[i*4+0]=g5.x*b1; sgr1[i*4+1]=g5.y*b1; sgr1[i*4+2]=g5.z*b1; sgr1[i*4+3]=g5.w*b1;
            }
            ull acc2[8];
#pragma unroll
            for (int g = 0; g < 8; g++) acc2[g] = 0ull;
#pragma unroll
            for (int c = 0; c < 16; c++) {
                float2 v2 = *(const float2*)&sm->sv[0][c][ux*2];
                float gv = sgr0[c];
                ull vg = pk2(v2.x * gv, v2.y * gv);
                float4 ka = *(const float4*)&sm->sk[0][c][uyy*8];
                float4 kb4 = *(const float4*)&sm->sk[0][c][uyy*8 + 4];
                acc2[0] = ffma2(pk2(ka.x, ka.x), vg, acc2[0]);
                acc2[1] = ffma2(pk2(ka.y, ka.y), vg, acc2[1]);
                acc2[2] = ffma2(pk2(ka.z, ka.z), vg, acc2[2]);
                acc2[3] = ffma2(pk2(ka.w, ka.w), vg, acc2[3]);
                acc2[4] = ffma2(pk2(kb4.x, kb4.x), vg, acc2[4]);
                acc2[5] = ffma2(pk2(kb4.y, kb4.y), vg, acc2[5]);
                acc2[6] = ffma2(pk2(kb4.z, kb4.z), vg, acc2[6]);
                acc2[7] = ffma2(pk2(kb4.w, kb4.w), vg, acc2[7]);
            }
#pragma unroll
            for (int c = 0; c < 16; c++) {
                float2 v2 = *(const float2*)&sm->sv[1][c][ux*2];
                float gv = sgr1[c];
                ull vg = pk2(v2.x * gv, v2.y * gv);
                float4 ka = *(const float4*)&sm->sk[1][c][uyy*8];
                float4 kb4 = *(const float4*)&sm->sk[1][c][uyy*8 + 4];
                acc2[0] = ffma2(pk2(ka.x, ka.x), vg, acc2[0]);
                acc2[1] = ffma2(pk2(ka.y, ka.y), vg, acc2[1]);
                acc2[2] = ffma2(pk2(ka.z, ka.z), vg, acc2[2]);
                acc2[3] = ffma2(pk2(ka.w, ka.w), vg, acc2[3]);
                acc2[4] = ffma2(pk2(kb4.x, kb4.x), vg, acc2[4]);
                acc2[5] = ffma2(pk2(kb4.y, kb4.y), vg, acc2[5]);
                acc2[6] = ffma2(pk2(kb4.z, kb4.z), vg, acc2[6]);
                acc2[7] = ffma2(pk2(kb4.w, kb4.w), vg, acc2[7]);
            }
            ull A2 = pk2(A, A);
#pragma unroll
            for (int g = 0; g < 8; g++) {
                ull cur = pk2(Cf[g][0], Cf[g][1]);
                ull nw  = ffma2(cur, A2, acc2[g]);
                upk2(nw, Cf[g][0], Cf[g][1]);
            }
            if (utid < 128) {
#pragma unroll
                for (int c = 0; c < 16; c++) {
                    ks = fmaf(sm->sk[0][c][utid], sgr0[c], ks);
                    ks = fmaf(sm->sk[1][c][utid], sgr1[c], ks);
                }
            }
        }
        __syncthreads();

        if (tid < 128) {
            // ---- epilogue for both chunks ----
            int c = tid >> 3, eq = tid & 7;
            float4 h0 = make_float4(0.f,0.f,0.f,0.f);
            float4 h1 = make_float4(0.f,0.f,0.f,0.f);
            float pn0 = 0.f, pn1 = 0.f;
#pragma unroll
            for (int w = 0; w < 8; w++) {
                float4 p0 = *(const float4*)&sm->spart[0][w][c][eq*4];
                h0.x += p0.x; h0.y += p0.y; h0.z += p0.z; h0.w += p0.w;
                float4 p1 = *(const float4*)&sm->spart[1][w][c][eq*4];
                h1.x += p1.x; h1.y += p1.y; h1.z += p1.z; h1.w += p1.w;
                pn0 += sm->spn[0][w][c];
                pn1 += sm->spn[1][w][c];
            }
            float norm0 = fmaxf(fabsf(res0 + rqs0*pn0), rxs0) + EPS_;
            float inv0 = 1.f / norm0;
            h0.x *= inv0; h0.y *= inv0; h0.z *= inv0; h0.w *= inv0;
            *(float4*)(out + rowbase + (size_t)(n0*16 + c)*DIM_ + et*ET_ + eq*4) = h0;
            float norm1 = fmaxf(fabsf(res1 + rqs1*pn1), rxs1) + EPS_;
            float inv1 = 1.f / norm1;
            h1.x *= inv1; h1.y *= inv1; h1.z *= inv1; h1.w *= inv1;
            *(float4*)(out + rowbase + (size_t)((n0+1)*16 + c)*DIM_ + et*ET_ + eq*4) = h1;
        } else if (tid >= 256) {
            // ---- republish C, sn update ----
#pragma unroll
            for (int g = 0; g < 8; g++)
                *(float2*)&sm->sC[uyy*8 + g][ux*2] = make_float2(Cf[g][0], Cf[g][1]);
            if (utid < 128)
                sm->sn[utid] = fmaf(sm->sn[utid], Acar, ks);
        }
        // loop-top barrier (after next stage) orders phase-2 writes
    }

    // ---- final states ----
    if (tid >= 256) {
        size_t clb = (size_t)bh * (DH_*DH_);
#pragma unroll
        for (int g = 0; g < 8; g++) {
            size_t o = clb + (size_t)(uyy*8 + g)*DH_ + et*ET_ + ux*2;
            *(float2*)&Cl[o] = make_float2(Cf[g][0], Cf[g][1]);
        }
        if (et == 0 && utid < 128) nl[bh*DH_ + utid] = sm->sn[utid];
    }
}

// ============================================================
// K5: in-place layernorm over out, per (b,s,head) row of 128.
// ============================================================
__global__ __launch_bounds__(256) void k_ln(
    const float* __restrict__ lnw, const float* __restrict__ lnb,
    float* __restrict__ out)
{
    int r = blockIdx.x*8 + (threadIdx.x >> 5);
    int lane = threadIdx.x & 31;
    int bs = r >> 3, h = r & 7;
    float4* p = (float4*)(out + (size_t)bs*DIM_ + h*DH_);
    float4 x = p[lane];
    float s1 = x.x + x.y + x.z + x.w;
#pragma unroll
    for (int off = 16; off; off >>= 1)
        s1 += __shfl_xor_sync(0xffffffffu, s1, off);
    float mu = s1 * (1.f/128.f);
    float dx = x.x - mu, dy = x.y - mu, dz = x.z - mu, dw = x.w - mu;
    float s2 = dx*dx + dy*dy + dz*dz + dw*dw;
#pragma unroll
    for (int off = 16; off; off >>= 1)
        s2 += __shfl_xor_sync(0xffffffffu, s2, off);
    float rstd = rsqrtf(s2 * (1.f/128.f) + LN_EPS_);
    float4 w = ((const float4*)(lnw + h*DH_))[lane];
    float4 bb = ((const float4*)(lnb + h*DH_))[lane];
    x.x = dx*rstd*(1.f + w.x) + bb.x;
    x.y = dy*rstd*(1.f + w.y) + bb.y;
    x.z = dz*rstd*(1.f + w.z) + bb.z;
    x.w = dw*rstd*(1.f + w.w) + bb.w;
    p[lane] = x;
}

// ============================================================
extern "C" void kernel_launch(void* const* d_in, const int* in_sizes, int n_in,
                              void* d_out, int out_size)
{
    const float* q   = (const float*)d_in[0];
    const float* k   = (const float*)d_in[1];
    const float* v   = (const float*)d_in[2];
    const float* Wi  = (const float*)d_in[3];
    const float* bi  = (const float*)d_in[4];
    const float* Wf  = (const float*)d_in[5];
    const float* bf  = (const float*)d_in[6];
    const float* lnw = (const float*)d_in[7];
    const float* lnb = (const float*)d_in[8];

    float* out = (float*)d_out;
    float* Cl  = out + (size_t)B_*S_*DIM_;
    float* nl  = Cl  + (size_t)BH_*DH_*DH_;
    float* ml  = nl  + (size_t)BH_*DH_;

    static int smem_set = 0;
    if (!smem_set) {
        cudaFuncSetAttribute(k_fused9,
            cudaFuncAttributeMaxDynamicSharedMemorySize, (int)sizeof(SM9));
        smem_set = 1;
    }

    k_gates  <<< (B_*S_)/K1_T, 256 >>>(q, k, v, Wi, bi, Wf, bf);
    k_prep   <<< BH_, 128 >>>(ml);
    k_phaseA <<< NCHUNK, 128 >>>(q, k);
    dim3 gf(4, BH_);
    k_fused9 <<< gf, 512, sizeof(SM9) >>>(q, k, v, out, Cl, nl);
    k_ln     <<< (B_*S_*NH_)/8, 256 >>>(lnw, lnb, out);
}

// round 12
// speedup vs baseline: 1.0997x; 1.0997x over previous
#include <cuda_runtime.h>
#include <math.h>

// ---------------- problem constants ----------------
#define B_    4
#define S_    2048
#define DIM_  1024
#define NH_   8
#define DH_   128
#define CS_   16
#define NS_   128
#define BH_   (B_*NH_)        // 32
#define NCHUNK (BH_*NS_)      // 4096
#define ET_   32              // e-tile width in fused kernel
#define EPS_    1e-6f
#define LN_EPS_ 1e-5f
#define NEG_   -1e30f
#define SCALE_ 0.08838834764831845f   // 1/sqrt(128)

typedef unsigned long long ull;

// ---------------- f32x2 packed helpers (sm_103a) ----------------
__device__ __forceinline__ ull pk2(float lo, float hi) {
    ull r; asm("mov.b64 %0, {%1, %2};" : "=l"(r) : "f"(lo), "f"(hi)); return r;
}
__device__ __forceinline__ ull ffma2(ull a, ull b, ull c) {
    ull d; asm("fma.rn.f32x2 %0, %1, %2, %3;" : "=l"(d) : "l"(a), "l"(b), "l"(c)); return d;
}
__device__ __forceinline__ ull fmul2(ull a, ull b) {
    ull d; asm("mul.rn.f32x2 %0, %1, %2;" : "=l"(d) : "l"(a), "l"(b)); return d;
}

// ---------------- scratch (device globals; no allocation) ----------------
__device__ float g_ig   [BH_*S_];
__device__ float g_fg   [BH_*S_];
__device__ float g_lfacc[BH_*S_];
__device__ float g_gexp [BH_*S_];
__device__ float g_mp   [NCHUNK];
__device__ float g_a    [NCHUNK];
__device__ float g_b    [NCHUNK];
__device__ float g_E    [NCHUNK*CS_*CS_]; // unnormalized E per chunk (16x16)
__device__ float g_qs   [NCHUNK*CS_];     // decay*scale per (chunk,c)
__device__ float g_esum [NCHUNK*CS_];     // row sums of E
__device__ float g_expns[NCHUNK*CS_];     // exp(-stab) per (chunk,c)

// ============================================================
// K1: gates (proven K1_T=8 config).
// ============================================================
#define K1_T 8
__global__ __launch_bounds__(256) void k_gates(
    const float* __restrict__ q, const float* __restrict__ k,
    const float* __restrict__ v, const float* __restrict__ Wi,
    const float* __restrict__ bi, const float* __restrict__ Wf,
    const float* __restrict__ bf)
{
    __shared__ float sg[K1_T][1024];
    int tid  = threadIdx.x;
    int base = blockIdx.x * K1_T;
    int w    = tid >> 5;
    int lane = tid & 31;
    const float* wi = Wi + w*3072;
    const float* wf = Wf + w*3072;

    float acc_i[K1_T], acc_f[K1_T];
#pragma unroll
    for (int t = 0; t < K1_T; t++) { acc_i[t] = 0.f; acc_f[t] = 0.f; }

    for (int seg = 0; seg < 3; seg++) {
        const float* src = (seg == 0) ? q : (seg == 1) ? k : v;
        for (int r = tid; r < K1_T*256; r += 256) {
            int t = r >> 8, d4 = r & 255;
            ((float4*)sg[t])[d4] =
                ((const float4*)(src + (size_t)(base + t)*1024))[d4];
        }
        __syncthreads();
        const float* wis = wi + seg*1024;
        const float* wfs = wf + seg*1024;
#pragma unroll 2
        for (int kk = lane*4; kk < 1024; kk += 128) {
            float4 w4i = *(const float4*)&wis[kk];
            float4 w4f = *(const float4*)&wfs[kk];
#pragma unroll
            for (int t = 0; t < K1_T; t++) {
                float4 g4 = *(const float4*)&sg[t][kk];
                acc_i[t] = fmaf(g4.x, w4i.x, acc_i[t]);
                acc_i[t] = fmaf(g4.y, w4i.y, acc_i[t]);
                acc_i[t] = fmaf(g4.z, w4i.z, acc_i[t]);
                acc_i[t] = fmaf(g4.w, w4i.w, acc_i[t]);
                acc_f[t] = fmaf(g4.x, w4f.x, acc_f[t]);
                acc_f[t] = fmaf(g4.y, w4f.y, acc_f[t]);
                acc_f[t] = fmaf(g4.z, w4f.z, acc_f[t]);
                acc_f[t] = fmaf(g4.w, w4f.w, acc_f[t]);
            }
        }
        __syncthreads();
    }
#pragma unroll
    for (int t = 0; t < K1_T; t++) {
#pragma unroll
        for (int off = 16; off; off >>= 1) {
            acc_i[t] += __shfl_xor_sync(0xffffffffu, acc_i[t], off);
            acc_f[t] += __shfl_xor_sync(0xffffffffu, acc_f[t], off);
        }
    }
    if (lane == 0) {
        float biv = bi[w], bfv = bf[w];
#pragma unroll
        for (int t = 0; t < K1_T; t++) {
            int bs = base + t;
            int b = bs >> 11, s = bs & 2047;
            int idx = (b*NH_ + w)*S_ + s;
            g_ig[idx] = acc_i[t] + biv;
            g_fg[idx] = acc_f[t] + bfv;
        }
    }
}

// ============================================================
// K2: per-bh prep: logsigmoid cumsum, gexp, (a,b,mp) max-plus scan.
// ============================================================
__global__ __launch_bounds__(128) void k_prep(float* __restrict__ ml_out)
{
    __shared__ float wLs[4], wMs[4];
    int bh = blockIdx.x;
    int n  = threadIdx.x;
    int lane = n & 31, wid = n >> 5;
    int base = bh*S_ + n*16;

    float fg[16], ig[16];
#pragma unroll
    for (int i = 0; i < 4; i++) {
        float4 f4 = *(const float4*)&g_fg[base + i*4];
        float4 i4 = *(const float4*)&g_ig[base + i*4];
        fg[i*4+0]=f4.x; fg[i*4+1]=f4.y; fg[i*4+2]=f4.z; fg[i*4+3]=f4.w;
        ig[i*4+0]=i4.x; ig[i*4+1]=i4.y; ig[i*4+2]=i4.z; ig[i*4+3]=i4.w;
    }
    float lfacc[16];
    float acc = 0.f;
#pragma unroll
    for (int c = 0; c < 16; c++) {
        float f = fg[c];
        float lf = fminf(f, 0.f) - log1pf(expf(-fabsf(f)));
        acc += lf;
        lfacc[c] = acc;
    }
    float lfl = lfacc[15];
    float lg[16];
    float mloc = NEG_;
#pragma unroll
    for (int c = 0; c < 16; c++) {
        lg[c] = ig[c] - lfacc[c] + lfl;
        mloc = fmaxf(mloc, lg[c]);
    }
#pragma unroll
    for (int i = 0; i < 4; i++) {
        float4 a4, g4;
        a4.x=lfacc[i*4+0]; a4.y=lfacc[i*4+1]; a4.z=lfacc[i*4+2]; a4.w=lfacc[i*4+3];
        g4.x=expf(lg[i*4+0]-mloc); g4.y=expf(lg[i*4+1]-mloc);
        g4.z=expf(lg[i*4+2]-mloc); g4.w=expf(lg[i*4+3]-mloc);
        *(float4*)&g_lfacc[base + i*4] = a4;
        *(float4*)&g_gexp [base + i*4] = g4;
    }

    float L = lfl, M = mloc;
#pragma unroll
    for (int off = 1; off < 32; off <<= 1) {
        float Lp = __shfl_up_sync(0xffffffffu, L, off);
        float Mp = __shfl_up_sync(0xffffffffu, M, off);
        if (lane >= off) { M = fmaxf(Mp + L, M); L = Lp + L; }
    }
    if (lane == 31) { wLs[wid] = L; wMs[wid] = M; }
    __syncthreads();
    float PL = 0.f, PM = NEG_;
#pragma unroll
    for (int ww = 0; ww < 4; ww++) {
        if (ww < wid) { PM = fmaxf(PM + wLs[ww], wMs[ww]); PL += wLs[ww]; }
    }
    float Lex_w = __shfl_up_sync(0xffffffffu, L, 1);
    float Mex_w = __shfl_up_sync(0xffffffffu, M, 1);
    if (lane == 0) { Lex_w = 0.f; Mex_w = NEG_; }
    float Lex = PL + Lex_w;
    float Mex = fmaxf(PM + Lex_w, Mex_w);
    float mp = fmaxf(Lex, Mex);
    float Linc = PL + L;
    float Minc = fmaxf(PM + L, M);
    float m = fmaxf(Linc, Minc);

    int idx = bh*NS_ + n;
    g_a [idx] = expf(lfl + mp - m);
    g_b [idx] = expf(mloc - m);
    g_mp[idx] = mp;
    if (n == NS_-1) ml_out[bh] = m;
}

// ============================================================
// K3: Phase A per chunk: unnormalized E, Esum, decay, exp(-stab).
// float4 global loads + float4 smem stores (PAD=132 keeps rows
// 16B-aligned); 4 vector loads/thread instead of 16 scalars.
// ============================================================
#define PAD 132
__global__ __launch_bounds__(128) void k_phaseA(
    const float* __restrict__ qin, const float* __restrict__ kin)
{
    __shared__ float sq [CS_][PAD];
    __shared__ float sk [CS_][PAD];
    __shared__ float slf[CS_], sig[CS_];
    __shared__ float smp;

    int chunk = blockIdx.x;
    int bh = chunk >> 7, n = chunk & 127;
    int b = bh >> 3, h = bh & 7;
    int tid = threadIdx.x;

#pragma unroll
    for (int r = tid; r < CS_*32; r += 128) {
        int c = r >> 5, d4 = (r & 31) * 4;
        size_t gidx = (size_t)(b*S_ + n*16 + c)*DIM_ + h*DH_ + d4;
        float4 qv = *(const float4*)(qin + gidx);
        qv.x *= SCALE_; qv.y *= SCALE_; qv.z *= SCALE_; qv.w *= SCALE_;
        *(float4*)&sq[c][d4] = qv;
        *(float4*)&sk[c][d4] = *(const float4*)(kin + gidx);
    }
    if (tid < 16) {
        slf[tid] = g_lfacc[bh*S_ + n*16 + tid];
        sig[tid] = g_ig  [bh*S_ + n*16 + tid];
    }
    if (tid == 0) smp = g_mp[chunk];
    __syncthreads();

    int c  = tid >> 3;
    int jj = tid & 7;
    int j0 = 2*jj, j1 = 2*jj + 1;
    float qk0 = 0.f, qk1 = 0.f;
#pragma unroll 4
    for (int d = 0; d < DH_; d++) {
        float qv = sq[c][d];
        qk0 = fmaf(qv, sk[j0][d], qk0);
        qk1 = fmaf(qv, sk[j1][d], qk1);
    }
    float mp  = smp;
    float lD0 = ((j0 > c) ? NEG_ : (slf[c] - slf[j0])) + sig[j0];
    float lD1 = ((j1 > c) ? NEG_ : (slf[c] - slf[j1])) + sig[j1];
    float mrow = fmaxf(lD0, lD1);
#pragma unroll
    for (int off = 4; off; off >>= 1)
        mrow = fmaxf(mrow, __shfl_xor_sync(0xffffffffu, mrow, off, 8));
    float stab  = fmaxf(mrow, mp + slf[c]);
    float decay = expf(mp + slf[c] - stab);
    float E0 = qk0 * expf(lD0 - stab);
    float E1 = qk1 * expf(lD1 - stab);
    float Esum = E0 + E1;
#pragma unroll
    for (int off = 4; off; off >>= 1)
        Esum += __shfl_xor_sync(0xffffffffu, Esum, off, 8);
    g_E[chunk*256 + c*16 + j0] = E0;
    g_E[chunk*256 + c*16 + j1] = E1;
    if (jj == 0) {
        g_qs   [chunk*16 + c] = decay * SCALE_;
        g_esum [chunk*16 + c] = Esum;
        g_expns[chunk*16 + c] = expf(-stab);
    }
}

// ============================================================
// K4: fused scan + output (v5 verbatim — proven 226us config).
//  warps 0-7 : inter  hraw = qs*(q@Cp) + E_un@v  (K-split), pn partials
//  warps 8-15: C state in regs; kv update; n-state scan; republish sC
// ============================================================
__global__ __launch_bounds__(512, 1) void k_fused5(
    const float* __restrict__ qin, const float* __restrict__ kin,
    const float* __restrict__ vin, float* __restrict__ out,
    float* __restrict__ Cl, float* __restrict__ nl)
{
    __shared__ float sq[CS_][132];
    __shared__ float sk[CS_][132];
    __shared__ float sv[CS_][36];
    __shared__ float sE[CS_][17];
    __shared__ float spart[8][CS_][36];
    __shared__ float spn[8][CS_];
    __shared__ float sC[DH_][ET_];
    __shared__ float sn[DH_];
    __shared__ float sgx[CS_], sqs[CS_];

    int et = blockIdx.x;      // 0..3
    int bh = blockIdx.y;      // 0..31
    int b = bh >> 3, h = bh & 7;
    int tid = threadIdx.x;
    int wid = tid >> 5;
    int lane = tid & 31;

    size_t rowbase = (size_t)(b*S_)*DIM_ + h*DH_;

    for (int i = tid; i < DH_*ET_; i += 512) (&sC[0][0])[i] = 0.f;
    if (tid < DH_) sn[tid] = 0.f;

    int c16 = tid >> 5, l32 = tid & 31;

    // inter role
    int cgi = lane >> 3, eg = lane & 7;
    // update role
    int utid = tid - 256;
    int ux = utid & 15, uyy = (utid >= 0) ? (utid >> 4) : 0;

    float Cf[8][2];
#pragma unroll
    for (int g = 0; g < 8; g++) { Cf[g][0] = 0.f; Cf[g][1] = 0.f; }

    // prefetch regs
    float4 qr, kr;
    float2 vr = make_float2(0.f, 0.f);
    float cE = 0.f, cg_ = 0.f, cqs = 0.f;
    float nab_a = 0.f, nab_b = 0.f;
    float nqs = 0.f, nes = 0.f, nxs = 0.f;

    {   // prefetch chunk 0
        int n = 0, chunk = bh*NS_;
        const float* qrow = qin + rowbase + (size_t)(n*16 + c16)*DIM_;
        const float* krow = kin + rowbase + (size_t)(n*16 + c16)*DIM_;
        qr = ((const float4*)qrow)[l32];
        kr = ((const float4*)krow)[l32];
        if (l32 < 16)
            vr = ((const float2*)(vin + rowbase + (size_t)(n*16 + c16)*DIM_ + et*ET_))[l32];
        if (tid < 256) cE = g_E[chunk*256 + tid];
        if (tid < 16) { cg_ = g_gexp[bh*S_ + n*16 + tid]; cqs = g_qs[chunk*16 + tid]; }
        if (tid >= 256) { nab_a = g_a[chunk]; nab_b = g_b[chunk]; }
        if (tid < 128) {
            int c = tid >> 3;
            nqs = g_qs[chunk*16 + c];
            nes = g_esum[chunk*16 + c];
            nxs = g_expns[chunk*16 + c];
        }
    }

    for (int n = 0; n < NS_; n++) {
        // ---- stage ----
        *(float4*)&sq[c16][l32*4] = qr;
        *(float4*)&sk[c16][l32*4] = kr;
        if (l32 < 16) *(float2*)&sv[c16][l32*2] = vr;
        if (tid < 256) sE[tid >> 4][tid & 15] = cE;
        if (tid < 16) { sgx[tid] = cg_; sqs[tid] = cqs; }
        float av = nab_a, bv = nab_b;
        float rqs = nqs, res = nes, rxs = nxs;
        __syncthreads();

        // ---- prefetch next ----
        if (n + 1 < NS_) {
            int n2 = n + 1, chunk2 = bh*NS_ + n2;
            const float* qrow = qin + rowbase + (size_t)(n2*16 + c16)*DIM_;
            const float* krow = kin + rowbase + (size_t)(n2*16 + c16)*DIM_;
            qr = ((const float4*)qrow)[l32];
            kr = ((const float4*)krow)[l32];
            if (l32 < 16)
                vr = ((const float2*)(vin + rowbase + (size_t)(n2*16 + c16)*DIM_ + et*ET_))[l32];
            if (tid < 256) cE = g_E[chunk2*256 + tid];
            if (tid < 16) { cg_ = g_gexp[bh*S_ + n2*16 + tid]; cqs = g_qs[chunk2*16 + tid]; }
            if (tid >= 256) { nab_a = g_a[chunk2]; nab_b = g_b[chunk2]; }
            if (tid < 128) {
                int c = tid >> 3;
                nqs = g_qs[chunk2*16 + c];
                nes = g_esum[chunk2*16 + c];
                nxs = g_expns[chunk2*16 + c];
            }
        }

        float ks = 0.f;
        if (tid < 256) {
            // ---- inter: vectorized K-split q@Cp + pn + E@v ----
            ull acc[4][2];
            float pnp[4];
#pragma unroll
            for (int i = 0; i < 4; i++) { acc[i][0] = 0ull; acc[i][1] = 0ull; pnp[i] = 0.f; }
            int k0 = wid * 16;
#pragma unroll
            for (int kk4 = 0; kk4 < 4; kk4++) {
                int kb = k0 + kk4*4;
                float4 qreg[4];
#pragma unroll
                for (int i = 0; i < 4; i++)
                    qreg[i] = *(const float4*)&sq[cgi + 4*i][kb];
                float4 sn4 = *(const float4*)&sn[kb];
#pragma unroll
                for (int j = 0; j < 4; j++) {
                    ulonglong2 c2 = *(const ulonglong2*)&sC[kb + j][eg*4];
                    float snv = ((const float*)&sn4)[j];
#pragma unroll
                    for (int i = 0; i < 4; i++) {
                        float qv = ((const float*)&qreg[i])[j];
                        ull q2 = pk2(qv, qv);
                        acc[i][0] = ffma2(q2, c2.x, acc[i][0]);
                        acc[i][1] = ffma2(q2, c2.y, acc[i][1]);
                        pnp[i] = fmaf(qv, snv, pnp[i]);
                    }
                }
            }
#pragma unroll
            for (int i = 0; i < 4; i++) {
                float qsv = sqs[cgi + 4*i];
                ull q2 = pk2(qsv, qsv);
                acc[i][0] = fmul2(acc[i][0], q2);
                acc[i][1] = fmul2(acc[i][1], q2);
            }
#pragma unroll
            for (int rr = 0; rr < 2; rr++) {
                int r = wid*2 + rr;
                ull vA = *(const ull*)&sv[r][eg*4];
                ull vB = *(const ull*)&sv[r][eg*4 + 2];
#pragma unroll
                for (int i = 0; i < 4; i++) {
                    float ev = sE[cgi + 4*i][r];
                    ull e2 = pk2(ev, ev);
                    acc[i][0] = ffma2(e2, vA, acc[i][0]);
                    acc[i][1] = ffma2(e2, vB, acc[i][1]);
                }
            }
#pragma unroll
            for (int i = 0; i < 4; i++) {
                ulonglong2 st; st.x = acc[i][0]; st.y = acc[i][1];
                *(ulonglong2*)&spart[wid][cgi + 4*i][eg*4] = st;
            }
            if (eg == 0) {
#pragma unroll
                for (int i = 0; i < 4; i++) spn[wid][cgi + 4*i] = pnp[i];
            }
        } else {
            // ---- update: Cf = a*Cf + b * k^T (v*gexp), packed ----
            float sgr[16];
#pragma unroll
            for (int i = 0; i < 4; i++) {
                float4 g4 = *(const float4*)&sgx[i*4];
                sgr[i*4+0]=g4.x; sgr[i*4+1]=g4.y; sgr[i*4+2]=g4.z; sgr[i*4+3]=g4.w;
            }
            ull acc2[8];
#pragma unroll
            for (int g = 0; g < 8; g++) acc2[g] = 0ull;
#pragma unroll
            for (int c = 0; c < 16; c++) {
                float2 v2 = *(const float2*)&sv[c][ux*2];
                float gv = sgr[c];
                ull vg = pk2(v2.x * gv, v2.y * gv);
                float4 ka = *(const float4*)&sk[c][uyy*8];
                float4 kb = *(const float4*)&sk[c][uyy*8 + 4];
                acc2[0] = ffma2(pk2(ka.x, ka.x), vg, acc2[0]);
                acc2[1] = ffma2(pk2(ka.y, ka.y), vg, acc2[1]);
                acc2[2] = ffma2(pk2(ka.z, ka.z), vg, acc2[2]);
                acc2[3] = ffma2(pk2(ka.w, ka.w), vg, acc2[3]);
                acc2[4] = ffma2(pk2(kb.x, kb.x), vg, acc2[4]);
                acc2[5] = ffma2(pk2(kb.y, kb.y), vg, acc2[5]);
                acc2[6] = ffma2(pk2(kb.z, kb.z), vg, acc2[6]);
                acc2[7] = ffma2(pk2(kb.w, kb.w), vg, acc2[7]);
            }
            ull a2 = pk2(av, av), b2 = pk2(bv, bv);
#pragma unroll
            for (int g = 0; g < 8; g++) {
                ull cur = pk2(Cf[g][0], Cf[g][1]);
                ull nw  = ffma2(cur, a2, fmul2(acc2[g], b2));
                float lo, hi;
                asm("mov.b64 {%0, %1}, %2;" : "=f"(lo), "=f"(hi) : "l"(nw));
                Cf[g][0] = lo; Cf[g][1] = hi;
            }
            if (utid < 128) {
#pragma unroll
                for (int c = 0; c < 16; c++)
                    ks = fmaf(sk[c][utid], sgr[c], ks);
            }
        }
        __syncthreads();

        if (tid < 128) {
            // ---- reduce partials + norm + store h ----
            int c = tid >> 3, eq = tid & 7;
            float4 hs = make_float4(0.f, 0.f, 0.f, 0.f);
#pragma unroll
            for (int w = 0; w < 8; w++) {
                float4 p = *(const float4*)&spart[w][c][eq*4];
                hs.x += p.x; hs.y += p.y; hs.z += p.z; hs.w += p.w;
            }
            float pn = 0.f;
#pragma unroll
            for (int w = 0; w < 8; w++) pn += spn[w][c];
            float norm = fmaxf(fabsf(res + rqs*pn), rxs) + EPS_;
            float inv = 1.f / norm;
            hs.x *= inv; hs.y *= inv; hs.z *= inv; hs.w *= inv;
            *(float4*)(out + rowbase + (size_t)(n*16 + c)*DIM_ + et*ET_ + eq*4) = hs;
        } else if (tid >= 256) {
#pragma unroll
            for (int g = 0; g < 8; g++)
                *(float2*)&sC[uyy*8 + g][ux*2] = make_float2(Cf[g][0], Cf[g][1]);
            if (utid < 128)
                sn[utid] = fmaf(sn[utid], av, ks * bv);
        }
    }

    // ---- final states ----
    if (tid >= 256) {
        size_t clb = (size_t)bh * (DH_*DH_);
#pragma unroll
        for (int g = 0; g < 8; g++) {
            size_t o = clb + (size_t)(uyy*8 + g)*DH_ + et*ET_ + ux*2;
            *(float2*)&Cl[o] = make_float2(Cf[g][0], Cf[g][1]);
        }
        if (et == 0 && utid < 128) nl[bh*DH_ + utid] = sn[utid];
    }
}

// ============================================================
// K5: in-place layernorm over out, per (b,s,head) row of 128.
// ============================================================
__global__ __launch_bounds__(256) void k_ln(
    const float* __restrict__ lnw, const float* __restrict__ lnb,
    float* __restrict__ out)
{
    int r = blockIdx.x*8 + (threadIdx.x >> 5);
    int lane = threadIdx.x & 31;
    int bs = r >> 3, h = r & 7;
    float4* p = (float4*)(out + (size_t)bs*DIM_ + h*DH_);
    float4 x = p[lane];
    float s1 = x.x + x.y + x.z + x.w;
#pragma unroll
    for (int off = 16; off; off >>= 1)
        s1 += __shfl_xor_sync(0xffffffffu, s1, off);
    float mu = s1 * (1.f/128.f);
    float dx = x.x - mu, dy = x.y - mu, dz = x.z - mu, dw = x.w - mu;
    float s2 = dx*dx + dy*dy + dz*dz + dw*dw;
#pragma unroll
    for (int off = 16; off; off >>= 1)
        s2 += __shfl_xor_sync(0xffffffffu, s2, off);
    float rstd = rsqrtf(s2 * (1.f/128.f) + LN_EPS_);
    float4 w = ((const float4*)(lnw + h*DH_))[lane];
    float4 bb = ((const float4*)(lnb + h*DH_))[lane];
    x.x = dx*rstd*(1.f + w.x) + bb.x;
    x.y = dy*rstd*(1.f + w.y) + bb.y;
    x.z = dz*rstd*(1.f + w.z) + bb.z;
    x.w = dw*rstd*(1.f + w.w) + bb.w;
    p[lane] = x;
}

// ============================================================
extern "C" void kernel_launch(void* const* d_in, const int* in_sizes, int n_in,
                              void* d_out, int out_size)
{
    const float* q   = (const float*)d_in[0];
    const float* k   = (const float*)d_in[1];
    const float* v   = (const float*)d_in[2];
    const float* Wi  = (const float*)d_in[3];
    const float* bi  = (const float*)d_in[4];
    const float* Wf  = (const float*)d_in[5];
    const float* bf  = (const float*)d_in[6];
    const float* lnw = (const float*)d_in[7];
    const float* lnb = (const float*)d_in[8];

    float* out = (float*)d_out;
    float* Cl  = out + (size_t)B_*S_*DIM_;
    float* nl  = Cl  + (size_t)BH_*DH_*DH_;
    float* ml  = nl  + (size_t)BH_*DH_;

    k_gates  <<< (B_*S_)/K1_T, 256 >>>(q, k, v, Wi, bi, Wf, bf);
    k_prep   <<< BH_, 128 >>>(ml);
    k_phaseA <<< NCHUNK, 128 >>>(q, k);
    dim3 gf(4, BH_);
    k_fused5 <<< gf, 512 >>>(q, k, v, out, Cl, nl);
    k_ln     <<< (B_*S_*NH_)/8, 256 >>>(lnw, lnb, out);
}

// round 13
// speedup vs baseline: 1.1011x; 1.0013x over previous
#include <cuda_runtime.h>
#include <math.h>

// ---------------- problem constants ----------------
#define B_    4
#define S_    2048
#define DIM_  1024
#define NH_   8
#define DH_   128
#define CS_   16
#define NS_   128
#define BH_   (B_*NH_)        // 32
#define NCHUNK (BH_*NS_)      // 4096
#define ET_   32              // e-tile width in fused kernel
#define EPS_    1e-6f
#define LN_EPS_ 1e-5f
#define NEG_   -1e30f
#define SCALE_ 0.08838834764831845f   // 1/sqrt(128)

typedef unsigned long long ull;

// ---------------- f32x2 packed helpers (sm_103a) ----------------
__device__ __forceinline__ ull pk2(float lo, float hi) {
    ull r; asm("mov.b64 %0, {%1, %2};" : "=l"(r) : "f"(lo), "f"(hi)); return r;
}
__device__ __forceinline__ ull ffma2(ull a, ull b, ull c) {
    ull d; asm("fma.rn.f32x2 %0, %1, %2, %3;" : "=l"(d) : "l"(a), "l"(b), "l"(c)); return d;
}
__device__ __forceinline__ ull fmul2(ull a, ull b) {
    ull d; asm("mul.rn.f32x2 %0, %1, %2;" : "=l"(d) : "l"(a), "l"(b)); return d;
}

// ---------------- scratch (device globals; no allocation) ----------------
__device__ float g_ig   [BH_*S_];
__device__ float g_fg   [BH_*S_];
__device__ float g_lfacc[BH_*S_];
__device__ float g_gexp [BH_*S_];
__device__ float g_mp   [NCHUNK];
__device__ float g_a    [NCHUNK];
__device__ float g_b    [NCHUNK];
__device__ float g_E    [NCHUNK*CS_*CS_]; // unnormalized E per chunk (16x16)
__device__ float g_qs   [NCHUNK*CS_];     // decay*scale per (chunk,c)
__device__ float g_esum [NCHUNK*CS_];     // row sums of E
__device__ float g_expns[NCHUNK*CS_];     // exp(-stab) per (chunk,c)

// ============================================================
// K1: gates (proven K1_T=8 config).
// ============================================================
#define K1_T 8
__global__ __launch_bounds__(256) void k_gates(
    const float* __restrict__ q, const float* __restrict__ k,
    const float* __restrict__ v, const float* __restrict__ Wi,
    const float* __restrict__ bi, const float* __restrict__ Wf,
    const float* __restrict__ bf)
{
    __shared__ float sg[K1_T][1024];
    int tid  = threadIdx.x;
    int base = blockIdx.x * K1_T;
    int w    = tid >> 5;
    int lane = tid & 31;
    const float* wi = Wi + w*3072;
    const float* wf = Wf + w*3072;

    float acc_i[K1_T], acc_f[K1_T];
#pragma unroll
    for (int t = 0; t < K1_T; t++) { acc_i[t] = 0.f; acc_f[t] = 0.f; }

    for (int seg = 0; seg < 3; seg++) {
        const float* src = (seg == 0) ? q : (seg == 1) ? k : v;
        for (int r = tid; r < K1_T*256; r += 256) {
            int t = r >> 8, d4 = r & 255;
            ((float4*)sg[t])[d4] =
                ((const float4*)(src + (size_t)(base + t)*1024))[d4];
        }
        __syncthreads();
        const float* wis = wi + seg*1024;
        const float* wfs = wf + seg*1024;
#pragma unroll 2
        for (int kk = lane*4; kk < 1024; kk += 128) {
            float4 w4i = *(const float4*)&wis[kk];
            float4 w4f = *(const float4*)&wfs[kk];
#pragma unroll
            for (int t = 0; t < K1_T; t++) {
                float4 g4 = *(const float4*)&sg[t][kk];
                acc_i[t] = fmaf(g4.x, w4i.x, acc_i[t]);
                acc_i[t] = fmaf(g4.y, w4i.y, acc_i[t]);
                acc_i[t] = fmaf(g4.z, w4i.z, acc_i[t]);
                acc_i[t] = fmaf(g4.w, w4i.w, acc_i[t]);
                acc_f[t] = fmaf(g4.x, w4f.x, acc_f[t]);
                acc_f[t] = fmaf(g4.y, w4f.y, acc_f[t]);
                acc_f[t] = fmaf(g4.z, w4f.z, acc_f[t]);
                acc_f[t] = fmaf(g4.w, w4f.w, acc_f[t]);
            }
        }
        __syncthreads();
    }
#pragma unroll
    for (int t = 0; t < K1_T; t++) {
#pragma unroll
        for (int off = 16; off; off >>= 1) {
            acc_i[t] += __shfl_xor_sync(0xffffffffu, acc_i[t], off);
            acc_f[t] += __shfl_xor_sync(0xffffffffu, acc_f[t], off);
        }
    }
    if (lane == 0) {
        float biv = bi[w], bfv = bf[w];
#pragma unroll
        for (int t = 0; t < K1_T; t++) {
            int bs = base + t;
            int b = bs >> 11, s = bs & 2047;
            int idx = (b*NH_ + w)*S_ + s;
            g_ig[idx] = acc_i[t] + biv;
            g_fg[idx] = acc_f[t] + bfv;
        }
    }
}

// ============================================================
// K2: per-bh prep: logsigmoid cumsum, gexp, (a,b,mp) max-plus scan.
// ============================================================
__global__ __launch_bounds__(128) void k_prep(float* __restrict__ ml_out)
{
    __shared__ float wLs[4], wMs[4];
    int bh = blockIdx.x;
    int n  = threadIdx.x;
    int lane = n & 31, wid = n >> 5;
    int base = bh*S_ + n*16;

    float fg[16], ig[16];
#pragma unroll
    for (int i = 0; i < 4; i++) {
        float4 f4 = *(const float4*)&g_fg[base + i*4];
        float4 i4 = *(const float4*)&g_ig[base + i*4];
        fg[i*4+0]=f4.x; fg[i*4+1]=f4.y; fg[i*4+2]=f4.z; fg[i*4+3]=f4.w;
        ig[i*4+0]=i4.x; ig[i*4+1]=i4.y; ig[i*4+2]=i4.z; ig[i*4+3]=i4.w;
    }
    float lfacc[16];
    float acc = 0.f;
#pragma unroll
    for (int c = 0; c < 16; c++) {
        float f = fg[c];
        float lf = fminf(f, 0.f) - log1pf(expf(-fabsf(f)));
        acc += lf;
        lfacc[c] = acc;
    }
    float lfl = lfacc[15];
    float lg[16];
    float mloc = NEG_;
#pragma unroll
    for (int c = 0; c < 16; c++) {
        lg[c] = ig[c] - lfacc[c] + lfl;
        mloc = fmaxf(mloc, lg[c]);
    }
#pragma unroll
    for (int i = 0; i < 4; i++) {
        float4 a4, g4;
        a4.x=lfacc[i*4+0]; a4.y=lfacc[i*4+1]; a4.z=lfacc[i*4+2]; a4.w=lfacc[i*4+3];
        g4.x=expf(lg[i*4+0]-mloc); g4.y=expf(lg[i*4+1]-mloc);
        g4.z=expf(lg[i*4+2]-mloc); g4.w=expf(lg[i*4+3]-mloc);
        *(float4*)&g_lfacc[base + i*4] = a4;
        *(float4*)&g_gexp [base + i*4] = g4;
    }

    float L = lfl, M = mloc;
#pragma unroll
    for (int off = 1; off < 32; off <<= 1) {
        float Lp = __shfl_up_sync(0xffffffffu, L, off);
        float Mp = __shfl_up_sync(0xffffffffu, M, off);
        if (lane >= off) { M = fmaxf(Mp + L, M); L = Lp + L; }
    }
    if (lane == 31) { wLs[wid] = L; wMs[wid] = M; }
    __syncthreads();
    float PL = 0.f, PM = NEG_;
#pragma unroll
    for (int ww = 0; ww < 4; ww++) {
        if (ww < wid) { PM = fmaxf(PM + wLs[ww], wMs[ww]); PL += wLs[ww]; }
    }
    float Lex_w = __shfl_up_sync(0xffffffffu, L, 1);
    float Mex_w = __shfl_up_sync(0xffffffffu, M, 1);
    if (lane == 0) { Lex_w = 0.f; Mex_w = NEG_; }
    float Lex = PL + Lex_w;
    float Mex = fmaxf(PM + Lex_w, Mex_w);
    float mp = fmaxf(Lex, Mex);
    float Linc = PL + L;
    float Minc = fmaxf(PM + L, M);
    float m = fmaxf(Linc, Minc);

    int idx = bh*NS_ + n;
    g_a [idx] = expf(lfl + mp - m);
    g_b [idx] = expf(mloc - m);
    g_mp[idx] = mp;
    if (n == NS_-1) ml_out[bh] = m;
}

// ============================================================
// K3: Phase A per chunk: unnormalized E, Esum, decay, exp(-stab).
// ============================================================
#define PAD 132
__global__ __launch_bounds__(128) void k_phaseA(
    const float* __restrict__ qin, const float* __restrict__ kin)
{
    __shared__ float sq [CS_][PAD];
    __shared__ float sk [CS_][PAD];
    __shared__ float slf[CS_], sig[CS_];
    __shared__ float smp;

    int chunk = blockIdx.x;
    int bh = chunk >> 7, n = chunk & 127;
    int b = bh >> 3, h = bh & 7;
    int tid = threadIdx.x;

#pragma unroll
    for (int r = tid; r < CS_*32; r += 128) {
        int c = r >> 5, d4 = (r & 31) * 4;
        size_t gidx = (size_t)(b*S_ + n*16 + c)*DIM_ + h*DH_ + d4;
        float4 qv = *(const float4*)(qin + gidx);
        qv.x *= SCALE_; qv.y *= SCALE_; qv.z *= SCALE_; qv.w *= SCALE_;
        *(float4*)&sq[c][d4] = qv;
        *(float4*)&sk[c][d4] = *(const float4*)(kin + gidx);
    }
    if (tid < 16) {
        slf[tid] = g_lfacc[bh*S_ + n*16 + tid];
        sig[tid] = g_ig  [bh*S_ + n*16 + tid];
    }
    if (tid == 0) smp = g_mp[chunk];
    __syncthreads();

    int c  = tid >> 3;
    int jj = tid & 7;
    int j0 = 2*jj, j1 = 2*jj + 1;
    float qk0 = 0.f, qk1 = 0.f;
#pragma unroll 4
    for (int d = 0; d < DH_; d++) {
        float qv = sq[c][d];
        qk0 = fmaf(qv, sk[j0][d], qk0);
        qk1 = fmaf(qv, sk[j1][d], qk1);
    }
    float mp  = smp;
    float lD0 = ((j0 > c) ? NEG_ : (slf[c] - slf[j0])) + sig[j0];
    float lD1 = ((j1 > c) ? NEG_ : (slf[c] - slf[j1])) + sig[j1];
    float mrow = fmaxf(lD0, lD1);
#pragma unroll
    for (int off = 4; off; off >>= 1)
        mrow = fmaxf(mrow, __shfl_xor_sync(0xffffffffu, mrow, off, 8));
    float stab  = fmaxf(mrow, mp + slf[c]);
    float decay = expf(mp + slf[c] - stab);
    float E0 = qk0 * expf(lD0 - stab);
    float E1 = qk1 * expf(lD1 - stab);
    float Esum = E0 + E1;
#pragma unroll
    for (int off = 4; off; off >>= 1)
        Esum += __shfl_xor_sync(0xffffffffu, Esum, off, 8);
    g_E[chunk*256 + c*16 + j0] = E0;
    g_E[chunk*256 + c*16 + j1] = E1;
    if (jj == 0) {
        g_qs   [chunk*16 + c] = decay * SCALE_;
        g_esum [chunk*16 + c] = Esum;
        g_expns[chunk*16 + c] = expf(-stab);
    }
}

// ============================================================
// K4: fused scan + output (v5 verbatim — proven 226us config).
//  warps 0-7 : inter  hraw = qs*(q@Cp) + E_un@v  (K-split), pn partials
//  warps 8-15: C state in regs; kv update; n-state scan; republish sC
// ============================================================
__global__ __launch_bounds__(512, 1) void k_fused5(
    const float* __restrict__ qin, const float* __restrict__ kin,
    const float* __restrict__ vin, float* __restrict__ out,
    float* __restrict__ Cl, float* __restrict__ nl)
{
    __shared__ float sq[CS_][132];
    __shared__ float sk[CS_][132];
    __shared__ float sv[CS_][36];
    __shared__ float sE[CS_][17];
    __shared__ float spart[8][CS_][36];
    __shared__ float spn[8][CS_];
    __shared__ float sC[DH_][ET_];
    __shared__ float sn[DH_];
    __shared__ float sgx[CS_], sqs[CS_];

    int et = blockIdx.x;      // 0..3
    int bh = blockIdx.y;      // 0..31
    int b = bh >> 3, h = bh & 7;
    int tid = threadIdx.x;
    int wid = tid >> 5;
    int lane = tid & 31;

    size_t rowbase = (size_t)(b*S_)*DIM_ + h*DH_;

    for (int i = tid; i < DH_*ET_; i += 512) (&sC[0][0])[i] = 0.f;
    if (tid < DH_) sn[tid] = 0.f;

    int c16 = tid >> 5, l32 = tid & 31;

    // inter role
    int cgi = lane >> 3, eg = lane & 7;
    // update role
    int utid = tid - 256;
    int ux = utid & 15, uyy = (utid >= 0) ? (utid >> 4) : 0;

    float Cf[8][2];
#pragma unroll
    for (int g = 0; g < 8; g++) { Cf[g][0] = 0.f; Cf[g][1] = 0.f; }

    // prefetch regs
    float4 qr, kr;
    float2 vr = make_float2(0.f, 0.f);
    float cE = 0.f, cg_ = 0.f, cqs = 0.f;
    float nab_a = 0.f, nab_b = 0.f;
    float nqs = 0.f, nes = 0.f, nxs = 0.f;

    {   // prefetch chunk 0
        int n = 0, chunk = bh*NS_;
        const float* qrow = qin + rowbase + (size_t)(n*16 + c16)*DIM_;
        const float* krow = kin + rowbase + (size_t)(n*16 + c16)*DIM_;
        qr = ((const float4*)qrow)[l32];
        kr = ((const float4*)krow)[l32];
        if (l32 < 16)
            vr = ((const float2*)(vin + rowbase + (size_t)(n*16 + c16)*DIM_ + et*ET_))[l32];
        if (tid < 256) cE = g_E[chunk*256 + tid];
        if (tid < 16) { cg_ = g_gexp[bh*S_ + n*16 + tid]; cqs = g_qs[chunk*16 + tid]; }
        if (tid >= 256) { nab_a = g_a[chunk]; nab_b = g_b[chunk]; }
        if (tid < 128) {
            int c = tid >> 3;
            nqs = g_qs[chunk*16 + c];
            nes = g_esum[chunk*16 + c];
            nxs = g_expns[chunk*16 + c];
        }
    }

    for (int n = 0; n < NS_; n++) {
        // ---- stage ----
        *(float4*)&sq[c16][l32*4] = qr;
        *(float4*)&sk[c16][l32*4] = kr;
        if (l32 < 16) *(float2*)&sv[c16][l32*2] = vr;
        if (tid < 256) sE[tid >> 4][tid & 15] = cE;
        if (tid < 16) { sgx[tid] = cg_; sqs[tid] = cqs; }
        float av = nab_a, bv = nab_b;
        float rqs = nqs, res = nes, rxs = nxs;
        __syncthreads();

        // ---- prefetch next ----
        if (n + 1 < NS_) {
            int n2 = n + 1, chunk2 = bh*NS_ + n2;
            const float* qrow = qin + rowbase + (size_t)(n2*16 + c16)*DIM_;
            const float* krow = kin + rowbase + (size_t)(n2*16 + c16)*DIM_;
            qr = ((const float4*)qrow)[l32];
            kr = ((const float4*)krow)[l32];
            if (l32 < 16)
                vr = ((const float2*)(vin + rowbase + (size_t)(n2*16 + c16)*DIM_ + et*ET_))[l32];
            if (tid < 256) cE = g_E[chunk2*256 + tid];
            if (tid < 16) { cg_ = g_gexp[bh*S_ + n2*16 + tid]; cqs = g_qs[chunk2*16 + tid]; }
            if (tid >= 256) { nab_a = g_a[chunk2]; nab_b = g_b[chunk2]; }
            if (tid < 128) {
                int c = tid >> 3;
                nqs = g_qs[chunk2*16 + c];
                nes = g_esum[chunk2*16 + c];
                nxs = g_expns[chunk2*16 + c];
            }
        }

        float ks = 0.f;
        if (tid < 256) {
            // ---- inter: vectorized K-split q@Cp + pn + E@v ----
            ull acc[4][2];
            float pnp[4];
#pragma unroll
            for (int i = 0; i < 4; i++) { acc[i][0] = 0ull; acc[i][1] = 0ull; pnp[i] = 0.f; }
            int k0 = wid * 16;
#pragma unroll
            for (int kk4 = 0; kk4 < 4; kk4++) {
                int kb = k0 + kk4*4;
                float4 qreg[4];
#pragma unroll
                for (int i = 0; i < 4; i++)
                    qreg[i] = *(const float4*)&sq[cgi + 4*i][kb];
                float4 sn4 = *(const float4*)&sn[kb];
#pragma unroll
                for (int j = 0; j < 4; j++) {
                    ulonglong2 c2 = *(const ulonglong2*)&sC[kb + j][eg*4];
                    float snv = ((const float*)&sn4)[j];
#pragma unroll
                    for (int i = 0; i < 4; i++) {
                        float qv = ((const float*)&qreg[i])[j];
                        ull q2 = pk2(qv, qv);
                        acc[i][0] = ffma2(q2, c2.x, acc[i][0]);
                        acc[i][1] = ffma2(q2, c2.y, acc[i][1]);
                        pnp[i] = fmaf(qv, snv, pnp[i]);
                    }
                }
            }
#pragma unroll
            for (int i = 0; i < 4; i++) {
                float qsv = sqs[cgi + 4*i];
                ull q2 = pk2(qsv, qsv);
                acc[i][0] = fmul2(acc[i][0], q2);
                acc[i][1] = fmul2(acc[i][1], q2);
            }
#pragma unroll
            for (int rr = 0; rr < 2; rr++) {
                int r = wid*2 + rr;
                ull vA = *(const ull*)&sv[r][eg*4];
                ull vB = *(const ull*)&sv[r][eg*4 + 2];
#pragma unroll
                for (int i = 0; i < 4; i++) {
                    float ev = sE[cgi + 4*i][r];
                    ull e2 = pk2(ev, ev);
                    acc[i][0] = ffma2(e2, vA, acc[i][0]);
                    acc[i][1] = ffma2(e2, vB, acc[i][1]);
                }
            }
#pragma unroll
            for (int i = 0; i < 4; i++) {
                ulonglong2 st; st.x = acc[i][0]; st.y = acc[i][1];
                *(ulonglong2*)&spart[wid][cgi + 4*i][eg*4] = st;
            }
            if (eg == 0) {
#pragma unroll
                for (int i = 0; i < 4; i++) spn[wid][cgi + 4*i] = pnp[i];
            }
        } else {
            // ---- update: Cf = a*Cf + b * k^T (v*gexp), packed ----
            float sgr[16];
#pragma unroll
            for (int i = 0; i < 4; i++) {
                float4 g4 = *(const float4*)&sgx[i*4];
                sgr[i*4+0]=g4.x; sgr[i*4+1]=g4.y; sgr[i*4+2]=g4.z; sgr[i*4+3]=g4.w;
            }
            ull acc2[8];
#pragma unroll
            for (int g = 0; g < 8; g++) acc2[g] = 0ull;
#pragma unroll
            for (int c = 0; c < 16; c++) {
                float2 v2 = *(const float2*)&sv[c][ux*2];
                float gv = sgr[c];
                ull vg = pk2(v2.x * gv, v2.y * gv);
                float4 ka = *(const float4*)&sk[c][uyy*8];
                float4 kb = *(const float4*)&sk[c][uyy*8 + 4];
                acc2[0] = ffma2(pk2(ka.x, ka.x), vg, acc2[0]);
                acc2[1] = ffma2(pk2(ka.y, ka.y), vg, acc2[1]);
                acc2[2] = ffma2(pk2(ka.z, ka.z), vg, acc2[2]);
                acc2[3] = ffma2(pk2(ka.w, ka.w), vg, acc2[3]);
                acc2[4] = ffma2(pk2(kb.x, kb.x), vg, acc2[4]);
                acc2[5] = ffma2(pk2(kb.y, kb.y), vg, acc2[5]);
                acc2[6] = ffma2(pk2(kb.z, kb.z), vg, acc2[6]);
                acc2[7] = ffma2(pk2(kb.w, kb.w), vg, acc2[7]);
            }
            ull a2 = pk2(av, av), b2 = pk2(bv, bv);
#pragma unroll
            for (int g = 0; g < 8; g++) {
                ull cur = pk2(Cf[g][0], Cf[g][1]);
                ull nw  = ffma2(cur, a2, fmul2(acc2[g], b2));
                float lo, hi;
                asm("mov.b64 {%0, %1}, %2;" : "=f"(lo), "=f"(hi) : "l"(nw));
                Cf[g][0] = lo; Cf[g][1] = hi;
            }
            if (utid < 128) {
#pragma unroll
                for (int c = 0; c < 16; c++)
                    ks = fmaf(sk[c][utid], sgr[c], ks);
            }
        }
        __syncthreads();

        if (tid < 128) {
            // ---- reduce partials + norm + store h ----
            int c = tid >> 3, eq = tid & 7;
            float4 hs = make_float4(0.f, 0.f, 0.f, 0.f);
#pragma unroll
            for (int w = 0; w < 8; w++) {
                float4 p = *(const float4*)&spart[w][c][eq*4];
                hs.x += p.x; hs.y += p.y; hs.z += p.z; hs.w += p.w;
            }
            float pn = 0.f;
#pragma unroll
            for (int w = 0; w < 8; w++) pn += spn[w][c];
            float norm = fmaxf(fabsf(res + rqs*pn), rxs) + EPS_;
            float inv = 1.f / norm;
            hs.x *= inv; hs.y *= inv; hs.z *= inv; hs.w *= inv;
            *(float4*)(out + rowbase + (size_t)(n*16 + c)*DIM_ + et*ET_ + eq*4) = hs;
        } else if (tid >= 256) {
#pragma unroll
            for (int g = 0; g < 8; g++)
                *(float2*)&sC[uyy*8 + g][ux*2] = make_float2(Cf[g][0], Cf[g][1]);
            if (utid < 128)
                sn[utid] = fmaf(sn[utid], av, ks * bv);
        }
    }

    // ---- final states ----
    if (tid >= 256) {
        size_t clb = (size_t)bh * (DH_*DH_);
#pragma unroll
        for (int g = 0; g < 8; g++) {
            size_t o = clb + (size_t)(uyy*8 + g)*DH_ + et*ET_ + ux*2;
            *(float2*)&Cl[o] = make_float2(Cf[g][0], Cf[g][1]);
        }
        if (et == 0 && utid < 128) nl[bh*DH_ + utid] = sn[utid];
    }
}

// ============================================================
// K5: in-place layernorm (v2): 2 rows per warp, single-pass
// stats (sum, sumsq reduced simultaneously; 5 shuffle steps,
// 4-wide ILP).
// ============================================================
__global__ __launch_bounds__(256) void k_ln(
    const float* __restrict__ lnw, const float* __restrict__ lnb,
    float* __restrict__ out)
{
    int warp = blockIdx.x*8 + (threadIdx.x >> 5);
    int lane = threadIdx.x & 31;
    int r0 = warp*2, r1 = r0 + 1;        // rows over B*S*NH
    int bs0 = r0 >> 3, h0 = r0 & 7;
    int bs1 = r1 >> 3, h1 = r1 & 7;
    float4* p0 = (float4*)(out + (size_t)bs0*DIM_ + h0*DH_);
    float4* p1 = (float4*)(out + (size_t)bs1*DIM_ + h1*DH_);
    float4 x0 = p0[lane];
    float4 x1 = p1[lane];

    float s1a = (x0.x + x0.y) + (x0.z + x0.w);
    float s2a = fmaf(x0.x, x0.x, fmaf(x0.y, x0.y, fmaf(x0.z, x0.z, x0.w*x0.w)));
    float s1b = (x1.x + x1.y) + (x1.z + x1.w);
    float s2b = fmaf(x1.x, x1.x, fmaf(x1.y, x1.y, fmaf(x1.z, x1.z, x1.w*x1.w)));
#pragma unroll
    for (int off = 16; off; off >>= 1) {
        s1a += __shfl_xor_sync(0xffffffffu, s1a, off);
        s2a += __shfl_xor_sync(0xffffffffu, s2a, off);
        s1b += __shfl_xor_sync(0xffffffffu, s1b, off);
        s2b += __shfl_xor_sync(0xffffffffu, s2b, off);
    }
    float mu0 = s1a * (1.f/128.f);
    float var0 = fmaxf(s2a * (1.f/128.f) - mu0*mu0, 0.f);
    float rstd0 = rsqrtf(var0 + LN_EPS_);
    float mu1 = s1b * (1.f/128.f);
    float var1 = fmaxf(s2b * (1.f/128.f) - mu1*mu1, 0.f);
    float rstd1 = rsqrtf(var1 + LN_EPS_);

    float4 w0 = ((const float4*)(lnw + h0*DH_))[lane];
    float4 b0 = ((const float4*)(lnb + h0*DH_))[lane];
    x0.x = (x0.x - mu0)*rstd0*(1.f + w0.x) + b0.x;
    x0.y = (x0.y - mu0)*rstd0*(1.f + w0.y) + b0.y;
    x0.z = (x0.z - mu0)*rstd0*(1.f + w0.z) + b0.z;
    x0.w = (x0.w - mu0)*rstd0*(1.f + w0.w) + b0.w;
    p0[lane] = x0;

    float4 w1 = ((const float4*)(lnw + h1*DH_))[lane];
    float4 b1 = ((const float4*)(lnb + h1*DH_))[lane];
    x1.x = (x1.x - mu1)*rstd1*(1.f + w1.x) + b1.x;
    x1.y = (x1.y - mu1)*rstd1*(1.f + w1.y) + b1.y;
    x1.z = (x1.z - mu1)*rstd1*(1.f + w1.z) + b1.z;
    x1.w = (x1.w - mu1)*rstd1*(1.f + w1.w) + b1.w;
    p1[lane] = x1;
}

// ============================================================
extern "C" void kernel_launch(void* const* d_in, const int* in_sizes, int n_in,
                              void* d_out, int out_size)
{
    const float* q   = (const float*)d_in[0];
    const float* k   = (const float*)d_in[1];
    const float* v   = (const float*)d_in[2];
    const float* Wi  = (const float*)d_in[3];
    const float* bi  = (const float*)d_in[4];
    const float* Wf  = (const float*)d_in[5];
    const float* bf  = (const float*)d_in[6];
    const float* lnw = (const float*)d_in[7];
    const float* lnb = (const float*)d_in[8];

    float* out = (float*)d_out;
    float* Cl  = out + (size_t)B_*S_*DIM_;
    float* nl  = Cl  + (size_t)BH_*DH_*DH_;
    float* ml  = nl  + (size_t)BH_*DH_;

    k_gates  <<< (B_*S_)/K1_T, 256 >>>(q, k, v, Wi, bi, Wf, bf);
    k_prep   <<< BH_, 128 >>>(ml);
    k_phaseA <<< NCHUNK, 128 >>>(q, k);
    dim3 gf(4, BH_);
    k_fused5 <<< gf, 512 >>>(q, k, v, out, Cl, nl);
    k_ln     <<< (B_*S_*NH_)/16, 256 >>>(lnw, lnb, out);
}